// round 1
// baseline (speedup 1.0000x reference)
#include <cuda_runtime.h>
#include <cuda_bf16.h>

// Problem constants (fixed by reference setup_inputs)
#define B_  4
#define C_  32
#define H_  96
#define W_  312
#define D_  48
#define W4_ (W_ / 4)          // 78 float4 per row
#define PAD_VALUE 1.0f

// One block per (b, c, h) row. Stage l-row and r-row in shared memory,
// then emit the D x W output plane for this row with float4 stores.
__global__ __launch_bounds__(256) void cost_volume_kernel(
    const float* __restrict__ l_fmap,
    const float* __restrict__ r_fmap,
    float* __restrict__ out)
{
    const int bid = blockIdx.x;            // 0 .. B*C*H-1
    const int h     = bid % H_;
    const int bc    = bid / H_;            // b*C + c

    __shared__ float l_row[W_];
    __shared__ float r_row[W_];

    const long long in_off = (long long)bid * W_;
    // load rows (312 floats each) cooperatively
    for (int i = threadIdx.x; i < W_; i += blockDim.x) {
        l_row[i] = __ldg(l_fmap + in_off + i);
        r_row[i] = __ldg(r_fmap + in_off + i);
    }
    __syncthreads();

    // Output layout: [B, C, D, H, W]
    // out_base for this (bc, h): bc*D*H*W + h*W ; per-d stride = H*W
    float* out_bc = out + (long long)bc * (D_ * H_ * W_) + (long long)h * W_;

    const int total = D_ * W4_;            // 3744 float4 stores per block
    for (int idx = threadIdx.x; idx < total; idx += blockDim.x) {
        const int d  = idx / W4_;
        const int w4 = idx - d * W4_;
        const int w  = w4 * 4;

        float4 v;
        // element j: w+j >= d ? l[w+j] - r[w+j-d] : PAD
        v.x = (w + 0 >= d) ? (l_row[w + 0] - r_row[w + 0 - d]) : PAD_VALUE;
        v.y = (w + 1 >= d) ? (l_row[w + 1] - r_row[w + 1 - d]) : PAD_VALUE;
        v.z = (w + 2 >= d) ? (l_row[w + 2] - r_row[w + 2 - d]) : PAD_VALUE;
        v.w = (w + 3 >= d) ? (l_row[w + 3] - r_row[w + 3 - d]) : PAD_VALUE;

        *reinterpret_cast<float4*>(out_bc + (long long)d * (H_ * W_) + w) = v;
    }
}

extern "C" void kernel_launch(void* const* d_in, const int* in_sizes, int n_in,
                              void* d_out, int out_size)
{
    const float* l_fmap = (const float*)d_in[0];
    const float* r_fmap = (const float*)d_in[1];
    float* out = (float*)d_out;

    const int blocks = B_ * C_ * H_;   // 12288
    cost_volume_kernel<<<blocks, 256>>>(l_fmap, r_fmap, out);
}

// round 2
// speedup vs baseline: 1.4354x; 1.4354x over previous
#include <cuda_runtime.h>
#include <cuda_bf16.h>

// Problem constants (fixed by reference setup_inputs)
#define B_  4
#define C_  32
#define H_  96
#define W_  312
#define D_  48
#define HW_ (H_ * W_)
#define W4_ (W_ / 4)          // 78 float4 per row
#define REP_PITCH (W_ + 4)    // 316 floats per shifted replica
#define PAD_VALUE 1.0f

// One block per (b, c, h) row.
//  - r row staged in shared 4x, replica s shifted right by s elements, so the
//    window r[w-d .. w-d+3] is one ALIGNED, conflict-free LDS.128 from
//    replica (d & 3) at element (w - 4*(d>>2)).
//  - l float4 lives in registers per thread (one global load, reused 48x).
//  - Output stored with __stcs (streaming; 736 MB, no reuse).
__global__ __launch_bounds__(96) void cost_volume_kernel(
    const float* __restrict__ l_fmap,
    const float* __restrict__ r_fmap,
    float* __restrict__ out)
{
    const int bid = blockIdx.x;            // 0 .. B*C*H-1
    const int h   = bid % H_;
    const int bc  = bid / H_;              // b*C + c

    __shared__ float rep[4][REP_PITCH];

    const long long in_off = (long long)bid * W_;
    const float* r_g = r_fmap + in_off;

    // Fill the 4 shifted replicas: rep[s][j+s] = r[j]
    for (int i = threadIdx.x; i < 4 * W_; i += 96) {
        const int s = i / W_;
        const int j = i - s * W_;
        rep[s][j + s] = __ldg(r_g + j);
    }
    __syncthreads();

    const int w4 = threadIdx.x;
    if (w4 >= W4_) return;
    const int w = w4 * 4;

    const float4 l4 = *reinterpret_cast<const float4*>(l_fmap + in_off + w);

    // Output layout [B, C, D, H, W]: base for (bc, h, w), per-d stride HW_
    float* outp = out + (long long)bc * (D_ * HW_) + (long long)h * W_ + w;

    #pragma unroll
    for (int q = 0; q < D_ / 4; ++q) {          // 12 groups of 4 disparities
        const int base_raw = w - 4 * q;
        const int base = base_raw < 0 ? 0 : base_raw;   // clamp (masked anyway)
        #pragma unroll
        for (int s = 0; s < 4; ++s) {
            const int d = 4 * q + s;
            const float4 r4 = *reinterpret_cast<const float4*>(&rep[s][base]);
            float4 v;
            v.x = (w + 0 >= d) ? (l4.x - r4.x) : PAD_VALUE;
            v.y = (w + 1 >= d) ? (l4.y - r4.y) : PAD_VALUE;
            v.z = (w + 2 >= d) ? (l4.z - r4.z) : PAD_VALUE;
            v.w = (w + 3 >= d) ? (l4.w - r4.w) : PAD_VALUE;
            __stcs(reinterpret_cast<float4*>(outp + (long long)d * HW_), v);
        }
    }
}

extern "C" void kernel_launch(void* const* d_in, const int* in_sizes, int n_in,
                              void* d_out, int out_size)
{
    const float* l_fmap = (const float*)d_in[0];
    const float* r_fmap = (const float*)d_in[1];
    float* out = (float*)d_out;

    const int blocks = B_ * C_ * H_;   // 12288
    cost_volume_kernel<<<blocks, 96>>>(l_fmap, r_fmap, out);
}

// round 5
// speedup vs baseline: 1.5084x; 1.0508x over previous
#include <cuda_runtime.h>
#include <cuda_bf16.h>

// Problem constants (fixed by reference setup_inputs)
#define B_   4
#define C_   32
#define H_   96
#define W_   312
#define D_   48
#define HW_  (H_ * W_)
#define W4_  (W_ / 4)           // 78 float4 per row
#define REP_PITCH (W_ + 4)      // 316 floats per shifted replica
#define ROWS 4                  // h-rows per block
#define NTHREADS 320            // 4*78=312 active
#define PAD_VALUE 1.0f

// One block per (bc, 4 consecutive h rows).
//  - Each r row staged in shared 4x; replica s is shifted right by s elements,
//    so the window r[w-d .. w-d+3] is one ALIGNED, conflict-free LDS.128 from
//    replica (d & 3) at element (w - 4*(d>>2)).
//  - l float4 lives in registers (one global load, reused for all 48 d).
//  - 4 consecutive h rows are contiguous in the output plane [H, W], so the
//    block's 312 lanes store one contiguous 4992B span per d-plane:
//    fully packed warps, fully coalesced streaming stores.
__global__ __launch_bounds__(NTHREADS) void cost_volume_kernel(
    const float* __restrict__ l_fmap,
    const float* __restrict__ r_fmap,
    float* __restrict__ out)
{
    const int bid = blockIdx.x;                 // 0 .. B*C*(H/ROWS)-1
    const int hb  = bid % (H_ / ROWS);          // row-group index
    const int bc  = bid / (H_ / ROWS);          // b*C + c
    const int h0  = hb * ROWS;

    __shared__ float rep[ROWS][4][REP_PITCH];

    const long long in_off = (long long)bc * HW_ + (long long)h0 * W_;
    const float* r_g = r_fmap + in_off;

    // Fill shifted replicas: rep[row][s][j+s] = r[row*W + j]
    // (ROWS * 4 * W_ = 4992 elements total)
    for (int i = threadIdx.x; i < ROWS * 4 * W_; i += NTHREADS) {
        const int row = i / (4 * W_);
        const int rem = i - row * (4 * W_);
        const int s   = rem / W_;
        const int j   = rem - s * W_;
        rep[row][s][j + s] = r_g[row * W_ + j];
    }
    __syncthreads();

    const int tid = threadIdx.x;
    if (tid >= ROWS * W4_) return;              // 312 active lanes
    const int row = tid / W4_;
    const int w4  = tid - row * W4_;
    const int w   = w4 * 4;

    const float4 l4 = *reinterpret_cast<const float4*>(l_fmap + in_off + row * W_ + w);

    // Output [B, C, D, H, W]: base for (bc, h0+row, w); per-d stride HW_
    float* outp = out + (long long)bc * (D_ * HW_)
                      + (long long)(h0 + row) * W_ + w;

    const float* reprow0 = &rep[row][0][0];     // replica s at reprow0 + s*REP_PITCH

    #pragma unroll
    for (int q = 0; q < D_ / 4; ++q) {          // 12 groups of 4 disparities
        const int base_raw = w - 4 * q;
        const int base = base_raw < 0 ? 0 : base_raw;   // clamped (masked anyway)
        #pragma unroll
        for (int s = 0; s < 4; ++s) {
            const int d = 4 * q + s;
            const float4 r4 = *reinterpret_cast<const float4*>(
                reprow0 + s * REP_PITCH + base);
            float4 v;
            v.x = (w + 0 >= d) ? (l4.x - r4.x) : PAD_VALUE;
            v.y = (w + 1 >= d) ? (l4.y - r4.y) : PAD_VALUE;
            v.z = (w + 2 >= d) ? (l4.z - r4.z) : PAD_VALUE;
            v.w = (w + 3 >= d) ? (l4.w - r4.w) : PAD_VALUE;
            __stcs(reinterpret_cast<float4*>(outp + (long long)d * HW_), v);
        }
    }
}

extern "C" void kernel_launch(void* const* d_in, const int* in_sizes, int n_in,
                              void* d_out, int out_size)
{
    const float* l_fmap = (const float*)d_in[0];
    const float* r_fmap = (const float*)d_in[1];
    float* out = (float*)d_out;

    const int blocks = B_ * C_ * (H_ / ROWS);   // 3072
    cost_volume_kernel<<<blocks, NTHREADS>>>(l_fmap, r_fmap, out);
}